// round 16
// baseline (speedup 1.0000x reference)
#include <cuda_runtime.h>
#include <cuda_fp16.h>
#include <cstdint>

// PolyConv: single persistent kernel; software grid barriers between phases.
// Phases: hist -> rows/fac -> init+scatter -> iter1(fp32,8-lane) -> iters2-4(fp16,4-lane).
// Grid sized to resident blocks via occupancy API (barrier-safe).
// Inputs: feat [N*32 f32], src [E i32], dst [E i32], mask [E f32]
// Output: h [N*32 f32]

#define N_NODES 100000
#define N_EDGES 1600000
#define DFEAT   32
#define DV4     (DFEAT / 4)
#define NV4     (N_NODES * DV4)
#define NH4     (N_NODES * 4)

// ---- scratch (static __device__, zero-init; invariants restored every call) ----
__device__ int      g_cnt[N_NODES];      // re-zeroed in rows phase
__device__ float    g_degf[N_NODES];     // re-zeroed in rows phase
__device__ int      g_total;             // re-zeroed after rows phase
__device__ unsigned g_bar_count;         // barrier state (returns to 0)
__device__ unsigned g_bar_gen;           // monotonically increasing (harmless)
__device__ int2     g_rows[N_NODES];
__device__ int      g_cursor[N_NODES];
__device__ float2   g_fac[N_NODES];      // {dinv^2, sqrt(max(deg,1))}
__device__ int2     g_edges[N_EDGES];
__device__ float4   g_src32[NV4];        // fp32 T0-scaled (iter1 gather source)
__device__ float4   g_scaled[NV4];       // fp32 state, in-place
__device__ uint4    g_halfA[NH4];        // fp16 mirror (ping)
__device__ uint4    g_halfB[NH4];        // fp16 mirror (pong)

static __device__ __forceinline__ unsigned h2u(__half2 h) {
    return *reinterpret_cast<unsigned*>(&h);
}

// sense-reversing software grid barrier (all blocks resident by construction)
static __device__ __forceinline__ void gbar() {
    __syncthreads();
    if (threadIdx.x == 0) {
        __threadfence();                                   // publish phase writes
        unsigned gen = *((volatile unsigned*)&g_bar_gen);  // capture BEFORE arrive
        unsigned arrived = atomicAdd(&g_bar_count, 1u);
        if (arrived == gridDim.x - 1) {
            g_bar_count = 0;
            __threadfence();
            *((volatile unsigned*)&g_bar_gen) = gen + 1;   // release
        } else {
            while (*((volatile unsigned*)&g_bar_gen) == gen) { __nanosleep(64); }
            __threadfence();                               // acquire
        }
    }
    __syncthreads();
}

// fp16-gather iteration body (4-lane groups)
static __device__ __forceinline__ void iter_body(
    int n, int c, float theta, const uint4* __restrict__ gin,
    uint4* __restrict__ gout, int write_next, float4* __restrict__ h4) {

    int2 rr = g_rows[n];

    float a0 = 0.f, a1 = 0.f, a2 = 0.f, a3 = 0.f;
    float a4 = 0.f, a5 = 0.f, a6 = 0.f, a7 = 0.f;

    #pragma unroll 8
    for (int j = rr.x; j < rr.y; ++j) {
        int2 ed = g_edges[j];
        float m = __int_as_float(ed.y);
        uint4 v = gin[ed.x * 4 + c];
        float2 f;
        f = __half22float2(*reinterpret_cast<__half2*>(&v.x)); a0 += f.x * m; a1 += f.y * m;
        f = __half22float2(*reinterpret_cast<__half2*>(&v.y)); a2 += f.x * m; a3 += f.y * m;
        f = __half22float2(*reinterpret_cast<__half2*>(&v.z)); a4 += f.x * m; a5 += f.y * m;
        f = __half22float2(*reinterpret_cast<__half2*>(&v.w)); a6 += f.x * m; a7 += f.y * m;
    }

    float2 fac = g_fac[n];
    float dinv2 = fac.x, rsq = fac.y;

    int i0 = n * DV4 + c * 2;
    float4 s0 = g_scaled[i0], s1 = g_scaled[i0 + 1];
    s0.x -= a0 * dinv2; s0.y -= a1 * dinv2; s0.z -= a2 * dinv2; s0.w -= a3 * dinv2;
    s1.x -= a4 * dinv2; s1.y -= a5 * dinv2; s1.z -= a6 * dinv2; s1.w -= a7 * dinv2;
    g_scaled[i0] = s0;
    g_scaled[i0 + 1] = s1;

    float tr = theta * rsq;
    float4 h0 = h4[i0], h1 = h4[i0 + 1];
    h0.x += tr * s0.x; h0.y += tr * s0.y; h0.z += tr * s0.z; h0.w += tr * s0.w;
    h1.x += tr * s1.x; h1.y += tr * s1.y; h1.z += tr * s1.z; h1.w += tr * s1.w;
    h4[i0] = h0;
    h4[i0 + 1] = h1;

    if (write_next) {
        uint4 hp;
        hp.x = h2u(__floats2half2_rn(s0.x, s0.y));
        hp.y = h2u(__floats2half2_rn(s0.z, s0.w));
        hp.z = h2u(__floats2half2_rn(s1.x, s1.y));
        hp.w = h2u(__floats2half2_rn(s1.z, s1.w));
        gout[n * 4 + c] = hp;
    }
}

__global__ void __launch_bounds__(256)
k_mono(const float4* __restrict__ feat4, const int* __restrict__ src,
       const int* __restrict__ dst, const float* __restrict__ mask,
       float4* __restrict__ h4, int E) {
    const int t  = threadIdx.x;
    const int gs = gridDim.x;
    const int lane = t & 31;

    // ---- Phase A: histogram (count + mask-sum per dst) ----
    for (int e = blockIdx.x * 256 + t; e < E; e += gs * 256) {
        int d = dst[e];
        atomicAdd(&g_cnt[d], 1);
        atomicAdd(&g_degf[d], mask[e]);
    }
    gbar();

    // ---- Phase B: row allocation (warp-aggregated) + factors + invariant reset ----
    for (int nb = blockIdx.x * 256; nb < N_NODES; nb += gs * 256) {
        int n = nb + t;
        int cnt = (n < N_NODES) ? g_cnt[n] : 0;

        int incl = cnt;
        #pragma unroll
        for (int o = 1; o < 32; o <<= 1) {
            int y = __shfl_up_sync(0xFFFFFFFFu, incl, o);
            if (lane >= o) incl += y;
        }
        int warp_base = 0;
        if (lane == 31) warp_base = atomicAdd(&g_total, incl);
        warp_base = __shfl_sync(0xFFFFFFFFu, warp_base, 31);

        if (n < N_NODES) {
            int base = warp_base + incl - cnt;
            g_rows[n] = make_int2(base, base + cnt);
            g_cursor[n] = base;
            float deg = fmaxf(g_degf[n], 1.0f);
            float dinv = rsqrtf(deg);
            g_fac[n] = make_float2(dinv * dinv, deg * dinv);  // {dinv^2, sqrt(deg)}
            g_cnt[n] = 0;                                      // restore invariant
            g_degf[n] = 0.0f;
        }
    }
    gbar();

    // ---- Phase C: src32 init + edge scatter (independent; merged) ----
    if (blockIdx.x == 0 && t == 0) g_total = 0;               // restore invariant
    for (int i = blockIdx.x * 256 + t; i < NV4; i += gs * 256) {
        int n = i >> 3;
        float2 fac = g_fac[n];
        float dinv = fac.x * fac.y;                           // deg^-1 * deg^1/2
        float4 f = feat4[i];
        float4 s;
        s.x = f.x * dinv; s.y = f.y * dinv; s.z = f.z * dinv; s.w = f.w * dinv;
        g_src32[i] = s;
    }
    for (int e = blockIdx.x * 256 + t; e < E; e += gs * 256) {
        int d = dst[e];
        int pos = atomicAdd(&g_cursor[d], 1);
        g_edges[pos] = make_int2(src[e], __float_as_int(mask[e]));
    }
    gbar();

    // ---- Phase D: iter1 (fp32 gather, 8-lane groups; h pure write) ----
    {
        const float theta0 = 0.2f, theta1 = -0.4f;
        for (int nb = blockIdx.x * 32; nb < N_NODES; nb += gs * 32) {
            int n = nb + (t >> 3);
            int c = t & 7;
            if (n < N_NODES) {
                int2 rr = g_rows[n];
                float a0 = 0.f, a1 = 0.f, a2 = 0.f, a3 = 0.f;
                #pragma unroll 4
                for (int j = rr.x; j < rr.y; ++j) {
                    int2 ed = g_edges[j];
                    float m = __int_as_float(ed.y);
                    float4 v = g_src32[ed.x * DV4 + c];
                    a0 += v.x * m; a1 += v.y * m; a2 += v.z * m; a3 += v.w * m;
                }
                float2 fac = g_fac[n];
                float dinv2 = fac.x, rsq = fac.y;
                int i = n * DV4 + c;
                float4 o = g_src32[i];
                float4 s;
                s.x = o.x - a0 * dinv2; s.y = o.y - a1 * dinv2;
                s.z = o.z - a2 * dinv2; s.w = o.w - a3 * dinv2;
                g_scaled[i] = s;
                float tpr = theta0 * rsq, tr = theta1 * rsq;
                float4 h;
                h.x = tpr * o.x + tr * s.x; h.y = tpr * o.y + tr * s.y;
                h.z = tpr * o.z + tr * s.z; h.w = tpr * o.w + tr * s.w;
                h4[i] = h;
                uint2 hp;
                hp.x = h2u(__floats2half2_rn(s.x, s.y));
                hp.y = h2u(__floats2half2_rn(s.z, s.w));
                reinterpret_cast<uint2*>(g_halfB)[n * 8 + c] = hp;
            }
        }
    }
    gbar();

    // ---- Phase E: iter2 (fp16 B -> state, mirror A) ----
    for (int nb = blockIdx.x * 64; nb < N_NODES; nb += gs * 64) {
        int n = nb + (t >> 2);
        if (n < N_NODES) iter_body(n, t & 3, 0.3f, g_halfB, g_halfA, 1, h4);
    }
    gbar();

    // ---- Phase F: iter3 (fp16 A -> state, mirror B) ----
    for (int nb = blockIdx.x * 64; nb < N_NODES; nb += gs * 64) {
        int n = nb + (t >> 2);
        if (n < N_NODES) iter_body(n, t & 3, -0.15f, g_halfA, g_halfB, 1, h4);
    }
    gbar();

    // ---- Phase G: iter4 (fp16 B, no mirror write) ----
    for (int nb = blockIdx.x * 64; nb < N_NODES; nb += gs * 64) {
        int n = nb + (t >> 2);
        if (n < N_NODES) iter_body(n, t & 3, 0.05f, g_halfB, g_halfA, 0, h4);
    }
}

extern "C" void kernel_launch(void* const* d_in, const int* in_sizes, int n_in,
                              void* d_out, int out_size) {
    const float* feat = (const float*)d_in[0];
    const int*   src  = (const int*)d_in[1];
    const int*   dst  = (const int*)d_in[2];
    const float* mask = (const float*)d_in[3];
    float* out = (float*)d_out;
    const int E = in_sizes[1];

    // grid = guaranteed-resident blocks (software barrier safety)
    int dev = 0, sms = 0, bpm = 0;
    cudaGetDevice(&dev);
    cudaDeviceGetAttribute(&sms, cudaDevAttrMultiProcessorCount, dev);
    cudaOccupancyMaxActiveBlocksPerMultiprocessor(&bpm, k_mono, 256, 0);
    if (sms <= 0) sms = 148;
    if (bpm <= 0) bpm = 4;
    int grid = sms * bpm;

    k_mono<<<grid, 256>>>((const float4*)feat, src, dst, mask, (float4*)out, E);
}

// round 17
// speedup vs baseline: 1.1746x; 1.1746x over previous
#include <cuda_runtime.h>
#include <cuda_fp16.h>
#include <cstdint>

// PolyConv: scan-free CSR build (packed 64-bit hist atomic) + atomic-free iters.
// iter1: 8-lane groups, fp32 gather; iters 2-4: 4-lane groups, fp16 mirrors.
// iter4 skips the dead state write.
// Inputs: feat [N*32 f32], src [E i32], dst [E i32], mask [E f32]
// Output: h [N*32 f32]

#define N_NODES 100000
#define N_EDGES 1600000
#define DFEAT   32
#define DV4     (DFEAT / 4)
#define NV4     (N_NODES * DV4)
#define NH4     (N_NODES * 4)

#define FIXSCALE 1048576.0f          // 2^20 fixed-point for mask sums
#define FIXINV   (1.0f / 1048576.0f)

// ---- scratch (static __device__, zero-init; invariants restored every call) ----
__device__ unsigned long long g_pack[N_NODES];  // {count:32 | masksum_fix:32}; re-zeroed in rows_init
__device__ int    g_total;               // row allocator; re-zeroed in iter4 tail
__device__ int2   g_rows[N_NODES];       // {base, end} of node's CSR segment
__device__ int    g_cursor[N_NODES];
__device__ float2 g_fac[N_NODES];        // {dinv^2, sqrt(max(deg,1))}
__device__ int2   g_edges[N_EDGES];      // CSR: {src, mask_bits} grouped by dst
__device__ float4 g_src32[NV4];          // fp32 gather source for iter1 (T0 scaled)
__device__ float4 g_scaled[NV4];         // fp32 state, in-place
__device__ uint4  g_halfA[NH4];          // fp16 gather mirror (ping)
__device__ uint4  g_halfB[NH4];          // fp16 gather mirror (pong)

static __device__ __forceinline__ unsigned h2u(__half2 h) {
    return *reinterpret_cast<unsigned*>(&h);
}

// ---------------------------------------------------------------------------
// histogram: ONE packed 64-bit atomic per edge (count<<32 | fixed-point mask)
__global__ void k_hist(const int* __restrict__ dst, const float* __restrict__ mask, int E) {
    int e = blockIdx.x * blockDim.x + threadIdx.x;
    if (e < E) {
        int d = dst[e];
        unsigned fix = __float2uint_rn(mask[e] * FIXSCALE);
        atomicAdd(&g_pack[d], (1ULL << 32) | (unsigned long long)fix);
    }
}

// rows + factors + init fused; also restores g_pack zero-invariant.
// Phase 1 (thread per node): warp-aggregated atomic row allocation, fac.
// Phase 2 (block-stride): src32 = feat * dinv (coalesced float4 writes).
__global__ void __launch_bounds__(256)
k_rows_init(const float4* __restrict__ feat4) {
    __shared__ float sh_dinv[256];
    int t = threadIdx.x;
    int lane = t & 31;
    int nb = blockIdx.x * 256;
    int n = nb + t;

    int cnt = 0;
    float degf = 0.0f;
    if (n < N_NODES) {
        unsigned long long p = g_pack[n];
        g_pack[n] = 0ULL;                              // restore invariant
        cnt = (int)(p >> 32);
        degf = (float)(unsigned)(p & 0xFFFFFFFFULL) * FIXINV;
    }

    int incl = cnt;
    #pragma unroll
    for (int o = 1; o < 32; o <<= 1) {
        int y = __shfl_up_sync(0xFFFFFFFFu, incl, o);
        if (lane >= o) incl += y;
    }
    int warp_base = 0;
    if (lane == 31) warp_base = atomicAdd(&g_total, incl);
    warp_base = __shfl_sync(0xFFFFFFFFu, warp_base, 31);

    float dinv = 0.0f;
    if (n < N_NODES) {
        int base = warp_base + incl - cnt;
        g_rows[n] = make_int2(base, base + cnt);
        g_cursor[n] = base;
        float deg = fmaxf(degf, 1.0f);
        dinv = rsqrtf(deg);
        g_fac[n] = make_float2(dinv * dinv, deg * dinv);   // {dinv^2, sqrt(deg)}
    }
    sh_dinv[t] = dinv;
    __syncthreads();

    for (int i = t; i < 256 * DV4; i += 256) {
        int nn = nb + (i >> 3);
        if (nn >= N_NODES) break;
        float dv = sh_dinv[i >> 3];
        int idx = nn * DV4 + (i & 7);
        float4 f = feat4[idx];
        float4 s;
        s.x = f.x * dv; s.y = f.y * dv; s.z = f.z * dv; s.w = f.w * dv;
        g_src32[idx] = s;
    }
}

__global__ void k_scatter(const int* __restrict__ src, const int* __restrict__ dst,
                          const float* __restrict__ mask, int E) {
    int e = blockIdx.x * blockDim.x + threadIdx.x;
    if (e >= E) return;
    int d = dst[e];
    int pos = atomicAdd(&g_cursor[d], 1);
    g_edges[pos] = make_int2(src[e], __float_as_int(mask[e]));
}

// iteration 1: 8-lane groups; fp32 gather = ONE 128B-line instruction per edge.
// h pure write; writes fp32 state + fp16 mirror (uint2 per lane).
__global__ void __launch_bounds__(256)
k_iter1(float4* __restrict__ h4, float theta0, float theta1) {
    int t = threadIdx.x;
    int n = blockIdx.x * 32 + (t >> 3);
    if (n >= N_NODES) return;
    int c = t & 7;

    int2 rr = g_rows[n];

    float a0 = 0.f, a1 = 0.f, a2 = 0.f, a3 = 0.f;

    #pragma unroll 4
    for (int j = rr.x; j < rr.y; ++j) {
        int2 ed = g_edges[j];
        float m = __int_as_float(ed.y);
        float4 v = g_src32[ed.x * DV4 + c];
        a0 += v.x * m; a1 += v.y * m; a2 += v.z * m; a3 += v.w * m;
    }

    float2 fac = g_fac[n];
    float dinv2 = fac.x, rsq = fac.y;

    int i = n * DV4 + c;
    float4 o = g_src32[i];
    float4 s;
    s.x = o.x - a0 * dinv2; s.y = o.y - a1 * dinv2;
    s.z = o.z - a2 * dinv2; s.w = o.w - a3 * dinv2;
    g_scaled[i] = s;

    float tpr = theta0 * rsq, tr = theta1 * rsq;
    float4 h;
    h.x = tpr * o.x + tr * s.x; h.y = tpr * o.y + tr * s.y;
    h.z = tpr * o.z + tr * s.z; h.w = tpr * o.w + tr * s.w;
    h4[i] = h;

    uint2 hp;
    hp.x = h2u(__floats2half2_rn(s.x, s.y));
    hp.y = h2u(__floats2half2_rn(s.z, s.w));
    reinterpret_cast<uint2*>(g_halfB)[n * 8 + c] = hp;
}

// iterations 2-4: 4-lane groups, fp16 gather, fp32 state, h RMW.
// sel: 1 -> in=halfA out=halfB, 0 -> in=halfB out=halfA.
// write_state: iter4 passes 0 (state dead afterwards).
// last: restore g_total zero-invariant.
__global__ void __launch_bounds__(256)
k_iter(float4* __restrict__ h4, float theta, int write_next, int sel,
       int write_state, int last) {
    const uint4* __restrict__ gin  = sel ? g_halfA : g_halfB;
    uint4* __restrict__       gout = sel ? g_halfB : g_halfA;

    int t = threadIdx.x;
    int n = blockIdx.x * 64 + (t >> 2);
    if (n >= N_NODES) return;
    int c = t & 3;

    int2 rr = g_rows[n];

    float a0 = 0.f, a1 = 0.f, a2 = 0.f, a3 = 0.f;
    float a4 = 0.f, a5 = 0.f, a6 = 0.f, a7 = 0.f;

    #pragma unroll 8
    for (int j = rr.x; j < rr.y; ++j) {
        int2 ed = g_edges[j];
        float m = __int_as_float(ed.y);
        uint4 v = gin[ed.x * 4 + c];
        float2 f;
        f = __half22float2(*reinterpret_cast<__half2*>(&v.x)); a0 += f.x * m; a1 += f.y * m;
        f = __half22float2(*reinterpret_cast<__half2*>(&v.y)); a2 += f.x * m; a3 += f.y * m;
        f = __half22float2(*reinterpret_cast<__half2*>(&v.z)); a4 += f.x * m; a5 += f.y * m;
        f = __half22float2(*reinterpret_cast<__half2*>(&v.w)); a6 += f.x * m; a7 += f.y * m;
    }

    float2 fac = g_fac[n];
    float dinv2 = fac.x, rsq = fac.y;

    int i0 = n * DV4 + c * 2;
    float4 s0 = g_scaled[i0], s1 = g_scaled[i0 + 1];
    s0.x -= a0 * dinv2; s0.y -= a1 * dinv2; s0.z -= a2 * dinv2; s0.w -= a3 * dinv2;
    s1.x -= a4 * dinv2; s1.y -= a5 * dinv2; s1.z -= a6 * dinv2; s1.w -= a7 * dinv2;
    if (write_state) {
        g_scaled[i0] = s0;
        g_scaled[i0 + 1] = s1;
    }

    float tr = theta * rsq;
    float4 h0 = h4[i0], h1 = h4[i0 + 1];
    h0.x += tr * s0.x; h0.y += tr * s0.y; h0.z += tr * s0.z; h0.w += tr * s0.w;
    h1.x += tr * s1.x; h1.y += tr * s1.y; h1.z += tr * s1.z; h1.w += tr * s1.w;
    h4[i0] = h0;
    h4[i0 + 1] = h1;

    if (write_next) {
        uint4 hp;
        hp.x = h2u(__floats2half2_rn(s0.x, s0.y));
        hp.y = h2u(__floats2half2_rn(s0.z, s0.w));
        hp.z = h2u(__floats2half2_rn(s1.x, s1.y));
        hp.w = h2u(__floats2half2_rn(s1.z, s1.w));
        gout[n * 4 + c] = hp;
    }

    if (last && n == 0 && c == 0) g_total = 0;   // restore invariant
}

extern "C" void kernel_launch(void* const* d_in, const int* in_sizes, int n_in,
                              void* d_out, int out_size) {
    const float* feat = (const float*)d_in[0];
    const int*   src  = (const int*)d_in[1];
    const int*   dst  = (const int*)d_in[2];
    const float* mask = (const float*)d_in[3];
    float* out = (float*)d_out;

    const int E = in_sizes[1];
    const int TB = 256;

    // --- CSR build (scan-free, packed hist) ---
    k_hist<<<(E + TB - 1) / TB, TB>>>(dst, mask, E);
    k_rows_init<<<(N_NODES + 255) / 256, 256>>>((const float4*)feat);
    k_scatter<<<(E + TB - 1) / TB, TB>>>(src, dst, mask, E);

    // --- 4 fused iterations ---  theta = {0.2, -0.4, 0.3, -0.15, 0.05}
    int node8_blocks = (N_NODES + 31) / 32;
    int node4_blocks = (N_NODES + 63) / 64;
    k_iter1<<<node8_blocks, TB>>>((float4*)out, 0.2f, -0.4f);        // mirror B
    k_iter<<<node4_blocks, TB>>>((float4*)out, 0.3f,   1, 0, 1, 0);  // B -> A
    k_iter<<<node4_blocks, TB>>>((float4*)out, -0.15f, 1, 1, 1, 0);  // A -> B
    k_iter<<<node4_blocks, TB>>>((float4*)out, 0.05f,  0, 0, 0, 1);  // B, no state write
}